// round 1
// baseline (speedup 1.0000x reference)
#include <cuda_runtime.h>

#define S_DIM 256
#define H_DIM 256
#define W_DIM 256
#define F_DIM 6
#define B_DIM 4096
// stride in floats between consecutive s for fixed (x,y)
#define S_STRIDE (H_DIM * W_DIM * F_DIM)

__global__ __launch_bounds__(128, 8)
void reward_er_kernel(const float* __restrict__ phi,
                      const float* __restrict__ w_lin,
                      const float* __restrict__ succ,
                      float* __restrict__ out) {
    const int b    = blockIdx.x;
    const int warp = threadIdx.x >> 5;   // 0..3
    const int lane = threadIdx.x & 31;

    // w_lin: 6 floats, tiny, cached
    const float w0 = __ldg(w_lin + 0);
    const float w1 = __ldg(w_lin + 1);
    const float w2 = __ldg(w_lin + 2);
    const float w3 = __ldg(w_lin + 3);
    const float w4 = __ldg(w_lin + 4);
    const float w5 = __ldg(w_lin + 5);

    // warp -> (t, ss/es):  warp0: t0 ss, warp1: t1 ss, warp2: t0 es, warp3: t1 es
    const int t     = warp & 1;
    const int is_es = warp >> 1;

    const float* p = phi + b * 20 + t * 10;  // phi is (B, 2, 10)
    const int x = (int)p[6 + 2 * is_es];
    const int y = (int)p[7 + 2 * is_es];

    const float* base = succ + ((x * W_DIM) + y) * F_DIM;

    // each lane handles s = lane + 32*i, i=0..7
    float v[8];
#pragma unroll
    for (int i = 0; i < 8; i++) {
        const int s = lane + 32 * i;
        const float* ptr = base + (long)s * S_STRIDE;
        const float2 a = __ldg((const float2*)(ptr + 0));
        const float2 c = __ldg((const float2*)(ptr + 2));
        const float2 d = __ldg((const float2*)(ptr + 4));
        v[i] = fmaf(a.x, w0, fmaf(a.y, w1,
               fmaf(c.x, w2, fmaf(c.y, w3,
               fmaf(d.x, w4, d.y * w5)))));
    }

    // softmax-weighted mean over the 256 s values held across the warp
    float m = v[0];
#pragma unroll
    for (int i = 1; i < 8; i++) m = fmaxf(m, v[i]);
#pragma unroll
    for (int off = 16; off > 0; off >>= 1)
        m = fmaxf(m, __shfl_xor_sync(0xffffffffu, m, off));

    float se = 0.0f, sev = 0.0f;
#pragma unroll
    for (int i = 0; i < 8; i++) {
        const float e = __expf(v[i] - m);
        se  += e;
        sev += e * v[i];
    }
#pragma unroll
    for (int off = 16; off > 0; off >>= 1) {
        se  += __shfl_xor_sync(0xffffffffu, se,  off);
        sev += __shfl_xor_sync(0xffffffffu, sev, off);
    }

    __shared__ float vres[4];  // [warp] = softmax-weighted value
    if (lane == 0) vres[warp] = sev / se;
    __syncthreads();

    if (threadIdx.x == 0) {
        // pr[t] = dot(phi[b,t,0:6], w)
        const float* p0 = phi + b * 20;
        const float* p1 = p0 + 10;
        const float pr0 = fmaf(p0[0], w0, fmaf(p0[1], w1, fmaf(p0[2], w2,
                          fmaf(p0[3], w3, fmaf(p0[4], w4, p0[5] * w5)))));
        const float pr1 = fmaf(p1[0], w0, fmaf(p1[1], w1, fmaf(p1[2], w2,
                          fmaf(p1[3], w3, fmaf(p1[4], w4, p1[5] * w5)))));

        const float v_ss0 = vres[0], v_ss1 = vres[1];
        const float v_es0 = vres[2], v_es1 = vres[3];

        const float left_der  = pr0 + (v_es0 - v_ss0);
        const float right_der = pr1 + (v_es1 - v_ss1);
        const float d = left_der - right_der;

        const float sp = 1.0f / (1.0f + expf(-d));  // sigmoid(d)
        const float sn = 1.0f / (1.0f + expf(d));   // sigmoid(-d)

        out[b * 2 + 0] = sp;
        out[b * 2 + 1] = sn;
    }
}

extern "C" void kernel_launch(void* const* d_in, const int* in_sizes, int n_in,
                              void* d_out, int out_size) {
    const float* phi   = (const float*)d_in[0];  // (B, 2, 10)
    const float* w_lin = (const float*)d_in[1];  // (1, 6)
    const float* succ  = (const float*)d_in[2];  // (S, H, W, F)
    float* out = (float*)d_out;                  // (B, 2, 1)

    reward_er_kernel<<<B_DIM, 128>>>(phi, w_lin, succ, out);
}